// round 16
// baseline (speedup 1.0000x reference)
#include <cuda_runtime.h>
#include <cuda_fp16.h>
#include <cstdint>

// Q/K/V: [16, 2048, 64] f32, R_w: [3,64], R_b: [3]; out: [16,2048,64] f32
#define S_LEN 2048
#define DH    64
#define NHEAD 16
#define BQ    128
#define BC    64
#define NT    256
#define PSTB  144           // padded f16 row stride in bytes (72 elems)
// C2 = (1/sqrt(512)) * log2(e)
#define C2 (0.04419417382415922f * 1.4426950408889634f)

// smem: THREE K/V buffers (cross-tile pipeline). Per buffer: KH 0, VH 9216.
#define BUFB   18432
#define OFF_VH 9216
#define SMEM_BYTES (3 * BUFB)

// ---- global scratch: f16 copies of K/V ----
__device__ __align__(16) __half g_Kh[NHEAD * S_LEN * DH];
__device__ __align__(16) __half g_Vh[NHEAD * S_LEN * DH];

// ---------------- helpers ----------------
static __device__ __forceinline__ uint32_t smem_u32(const void* p) {
    uint32_t a;
    asm("{ .reg .u64 t; cvta.to.shared.u64 t, %1; cvt.u32.u64 %0, t; }" : "=r"(a) : "l"(p));
    return a;
}
static __device__ __forceinline__ void ldm_x4(uint32_t* r, uint32_t addr) {
    asm volatile("ldmatrix.sync.aligned.m8n8.x4.shared.b16 {%0,%1,%2,%3}, [%4];"
        : "=r"(r[0]), "=r"(r[1]), "=r"(r[2]), "=r"(r[3]) : "r"(addr));
}
static __device__ __forceinline__ void ldm_x4_t(uint32_t* r, uint32_t addr) {
    asm volatile("ldmatrix.sync.aligned.m8n8.x4.trans.shared.b16 {%0,%1,%2,%3}, [%4];"
        : "=r"(r[0]), "=r"(r[1]), "=r"(r[2]), "=r"(r[3]) : "r"(addr));
}
static __device__ __forceinline__ void mma16816(float* d, const uint32_t* a, uint32_t b0, uint32_t b1) {
    asm volatile("mma.sync.aligned.m16n8k16.row.col.f32.f16.f16.f32 "
        "{%0,%1,%2,%3}, {%4,%5,%6,%7}, {%8,%9}, {%0,%1,%2,%3};"
        : "+f"(d[0]), "+f"(d[1]), "+f"(d[2]), "+f"(d[3])
        : "r"(a[0]), "r"(a[1]), "r"(a[2]), "r"(a[3]), "r"(b0), "r"(b1));
}
static __device__ __forceinline__ uint32_t pkh(float a, float b) {
    __half2 t = __floats2half2_rn(a, b);     // a -> low half
    return *reinterpret_cast<uint32_t*>(&t);
}
static __device__ __forceinline__ float ex2f(float x) {
    float r; asm("ex2.approx.f32 %0, %1;" : "=f"(r) : "f"(x)); return r;
}
#define CP16(dst, src) \
    asm volatile("cp.async.cg.shared.global [%0], [%1], 16;" :: "r"(dst), "l"(src))
#define CP_COMMIT() asm volatile("cp.async.commit_group;" ::: "memory")
#define CP_WAIT(n)  asm volatile("cp.async.wait_group %0;" :: "n"(n) : "memory")

// ---------------- pre-pass: K/V f32 -> f16, MLP=4 ----------------
__global__ void prepass_cvt(const float* __restrict__ K, const float* __restrict__ V)
{
    const int N4 = NHEAD * S_LEN * DH / 4;   // 524288
    const int HALF = N4 / 2;                 // 262144
    const int j = blockIdx.x * blockDim.x + threadIdx.x;   // 0..262143
    const float4* K4 = (const float4*)K;
    const float4* V4 = (const float4*)V;
    float4 k0 = K4[j], k1 = K4[j + HALF];
    float4 v0 = V4[j], v1 = V4[j + HALF];
    uint2* Kd = (uint2*)g_Kh;
    uint2* Vd = (uint2*)g_Vh;
    Kd[j]        = make_uint2(pkh(k0.x, k0.y), pkh(k0.z, k0.w));
    Kd[j + HALF] = make_uint2(pkh(k1.x, k1.y), pkh(k1.z, k1.w));
    Vd[j]        = make_uint2(pkh(v0.x, v0.y), pkh(v0.z, v0.w));
    Vd[j + HALF] = make_uint2(pkh(v1.x, v1.y), pkh(v1.z, v1.w));
}

// issue K+V tile kt into buffer (NT=256: 2+2 CP16 per thread)
static __device__ __forceinline__ void issue_kv(uint32_t sbuf, int b, int kt, int tid) {
    const int row = tid >> 2, h = (tid & 3) * 32;          // 32B quarter-row
    const size_t boff = ((size_t)(b * S_LEN + kt * BC + row)) * (DH * 2) + h;
    const uint32_t d = sbuf + row * PSTB + h;
    CP16(d,               (const char*)g_Kh + boff);
    CP16(d + 16,          (const char*)g_Kh + boff + 16);
    CP16(d + OFF_VH,      (const char*)g_Vh + boff);
    CP16(d + OFF_VH + 16, (const char*)g_Vh + boff + 16);
}

extern __shared__ char smdyn[];

__global__ __launch_bounds__(NT, 2)
void attn_main(const float* __restrict__ Q, const float* __restrict__ Rw,
               const float* __restrict__ Rb, float* __restrict__ Out)
{
    const int tid  = threadIdx.x;
    const int lane = tid & 31;
    const int w    = tid >> 5;       // 8 warps, warp w owns rows w*16..w*16+15

    // R10 schedule: classes (bid%148) >= 108 solo with the 40 longest jobs;
    // paired classes boustrophedon.
    int rank;
    {
        const int bid = (int)blockIdx.x;
        const int cls = bid % 148, inst = bid / 148;
        if (cls >= 108)  rank = cls - 108;                // solo: ranks 0..39
        else             rank = inst ? (255 - cls) : (40 + cls);
    }
    const int qt = 15 - (rank >> 4);       // longest (qt=15) at rank 0
    const int b  = rank & 15;
    const int ntiles = 2 * qt + 2;
    const uint32_t sb = smem_u32(smdyn);

    // ---- prologue: prefetch K/V tiles 0 and 1 ----
    issue_kv(sb, b, 0, tid);
    CP_COMMIT();
    issue_kv(sb + BUFB, b, 1, tid);
    CP_COMMIT();

    // ---- biases from f32 Q, in-warp ----
    const int g = lane >> 2, tg = lane & 3;
    const int grow0 = qt * BQ + w * 16 + g;
    const int grow1 = grow0 + 8;
    const int wmin  = qt * BQ + w * 16;        // warp's min query row
    const int wmax  = wmin + 15;               // warp's max query row
    float bb0_0, bb1_0, bb0_1, bb1_1;
    {
        const int r = lane >> 1, h = (lane & 1) * 32;
        const float* q = Q + ((size_t)(b * S_LEN + qt * BQ + w * 16 + r)) * DH + h;
        float s0 = 0.f, s1 = 0.f;
        #pragma unroll
        for (int i = 0; i < 8; ++i) {
            float4 v = reinterpret_cast<const float4*>(q)[i];
            const int cc = h + 4 * i;
            s0 = fmaf(v.x, __ldg(Rw + cc+0), s0); s0 = fmaf(v.y, __ldg(Rw + cc+1), s0);
            s0 = fmaf(v.z, __ldg(Rw + cc+2), s0); s0 = fmaf(v.w, __ldg(Rw + cc+3), s0);
            s1 = fmaf(v.x, __ldg(Rw + 64+cc+0), s1); s1 = fmaf(v.y, __ldg(Rw + 64+cc+1), s1);
            s1 = fmaf(v.z, __ldg(Rw + 64+cc+2), s1); s1 = fmaf(v.w, __ldg(Rw + 64+cc+3), s1);
        }
        s0 += __shfl_xor_sync(0xFFFFFFFFu, s0, 1);
        s1 += __shfl_xor_sync(0xFFFFFFFFu, s1, 1);
        s0 = (s0 + __ldg(Rb + 0)) * C2;
        s1 = (s1 + __ldg(Rb + 1)) * C2;
        bb0_0 = __shfl_sync(0xFFFFFFFFu, s0, 2 * g);
        bb1_0 = __shfl_sync(0xFFFFFFFFu, s1, 2 * g);
        bb0_1 = __shfl_sync(0xFFFFFFFFu, s0, 2 * g + 16);
        bb1_1 = __shfl_sync(0xFFFFFFFFu, s1, 2 * g + 16);
    }

    // ---- Q fragments straight from f32 global ----
    uint32_t qf[4][4];
    {
        const float* Qlo = Q + ((size_t)(b * S_LEN + grow0)) * DH;
        const float* Qhi = Q + ((size_t)(b * S_LEN + grow1)) * DH;
        #pragma unroll
        for (int k16 = 0; k16 < 4; ++k16) {
            const int cc = k16 * 16 + tg * 2;
            float2 vlo0 = *reinterpret_cast<const float2*>(Qlo + cc);
            float2 vhi0 = *reinterpret_cast<const float2*>(Qhi + cc);
            float2 vlo1 = *reinterpret_cast<const float2*>(Qlo + cc + 8);
            float2 vhi1 = *reinterpret_cast<const float2*>(Qhi + cc + 8);
            qf[k16][0] = pkh(vlo0.x, vlo0.y);
            qf[k16][1] = pkh(vhi0.x, vhi0.y);
            qf[k16][2] = pkh(vlo1.x, vlo1.y);
            qf[k16][3] = pkh(vhi1.x, vhi1.y);
        }
    }

    float o[8][4];
    #pragma unroll
    for (int n = 0; n < 8; ++n)
        #pragma unroll
        for (int e = 0; e < 4; ++e) o[n][e] = 0.f;
    float rs0 = 0.f, rs1 = 0.f;

    const int rowK  = ((lane & 16) ? 8 : 0) + (lane & 7);
    const int colK8 = (lane & 8) ? 8 : 0;
    const int rowV  = lane & 15;
    const int colV8 = (lane & 16) ? 8 : 0;

    // softmax of tile t from s -> pf (macro-ish lambda; fast path iff all keys < wmin)
    uint32_t pf[4][4];
    auto softmax_tile = [&](int t, float sarr[8][4]) {
        const int kbase = t * BC;
        if (kbase + (BC - 1) < wmin) {              // strictly below: bias0 everywhere
            #pragma unroll
            for (int k16 = 0; k16 < 4; ++k16)
                #pragma unroll
                for (int e = 0; e < 2; ++e) {
                    float* sv = sarr[2*k16 + e];
                    float p0 = ex2f(fmaf(sv[0], C2, bb0_0));
                    float p1 = ex2f(fmaf(sv[1], C2, bb0_0));
                    float p2 = ex2f(fmaf(sv[2], C2, bb0_1));
                    float p3 = ex2f(fmaf(sv[3], C2, bb0_1));
                    rs0 += p0 + p1; rs1 += p2 + p3;
                    pf[k16][2*e]     = pkh(p0, p1);
                    pf[k16][2*e + 1] = pkh(p2, p3);
                }
        } else {
            #pragma unroll
            for (int k16 = 0; k16 < 4; ++k16)
                #pragma unroll
                for (int e = 0; e < 2; ++e) {
                    float* sv = sarr[2*k16 + e];
                    const int c0 = kbase + (2*k16 + e) * 8 + tg * 2;
                    const int c1 = c0 + 1;
                    float p0 = (c0 > grow0) ? 0.f : ex2f(fmaf(sv[0], C2, (c0 == grow0) ? bb1_0 : bb0_0));
                    float p1 = (c1 > grow0) ? 0.f : ex2f(fmaf(sv[1], C2, (c1 == grow0) ? bb1_0 : bb0_0));
                    float p2 = (c0 > grow1) ? 0.f : ex2f(fmaf(sv[2], C2, (c0 == grow1) ? bb1_1 : bb0_1));
                    float p3 = (c1 > grow1) ? 0.f : ex2f(fmaf(sv[3], C2, (c1 == grow1) ? bb1_1 : bb0_1));
                    rs0 += p0 + p1; rs1 += p2 + p3;
                    pf[k16][2*e]     = pkh(p0, p1);
                    pf[k16][2*e + 1] = pkh(p2, p3);
                }
        }
    };

    CP_WAIT(0);
    __syncthreads();           // tiles 0 and 1 visible

    // ---- prologue compute: S(0) + softmax(0) -> pf ----
    {
        float s[8][4];
        #pragma unroll
        for (int n = 0; n < 8; ++n)
            #pragma unroll
            for (int e = 0; e < 4; ++e) s[n][e] = 0.f;
        #pragma unroll
        for (int k16 = 0; k16 < 4; ++k16)
            #pragma unroll
            for (int j = 0; j < 4; ++j) {
                const uint32_t ak = sb + (uint32_t)((16 * j + rowK) * PSTB)
                                  + (uint32_t)((k16 * 16 + colK8) * 2);
                uint32_t kh[4];
                ldm_x4(kh, ak);
                mma16816(s[2*j],   qf[k16], kh[0], kh[1]);
                mma16816(s[2*j+1], qf[k16], kh[2], kh[3]);
            }
        softmax_tile(0, s);
    }

    for (int kt = 0; kt < ntiles; ++kt) {
        const uint32_t bufPV = sb + (uint32_t)((kt % 3) * BUFB);
        const int has_next = (kt + 1 < ntiles);
        const uint32_t bufS = sb + (uint32_t)(((kt + 1) % 3) * BUFB);

        if (kt + 2 < ntiles) {
            issue_kv(sb + (uint32_t)(((kt + 2) % 3) * BUFB), b, kt + 2, tid);
            CP_COMMIT();
        }

        const int doS  = has_next && ((kt + 1) * BC <= wmax);   // next tile not fully masked
        const int doPV = (kt * BC <= wmax);

        // ---- interleaved: PV(kt) with pf, S(kt+1) into s ----
        float s[8][4];
        #pragma unroll
        for (int n = 0; n < 8; ++n)
            #pragma unroll
            for (int e = 0; e < 4; ++e) s[n][e] = 0.f;

        #pragma unroll
        for (int k16 = 0; k16 < 4; ++k16) {
            if (doS) {
                #pragma unroll
                for (int j = 0; j < 4; ++j) {
                    const uint32_t ak = bufS + (uint32_t)((16 * j + rowK) * PSTB)
                                      + (uint32_t)((k16 * 16 + colK8) * 2);
                    uint32_t kh[4];
                    ldm_x4(kh, ak);
                    mma16816(s[2*j],   qf[k16], kh[0], kh[1]);
                    mma16816(s[2*j+1], qf[k16], kh[2], kh[3]);
                }
            }
            if (doPV) {
                #pragma unroll
                for (int j = 0; j < 4; ++j) {
                    const uint32_t av = bufPV + OFF_VH + (uint32_t)((16 * k16 + rowV) * PSTB)
                                      + (uint32_t)((16 * j + colV8) * 2);
                    uint32_t vh[4];
                    ldm_x4_t(vh, av);
                    mma16816(o[2*j],   pf[k16], vh[0], vh[1]);
                    mma16816(o[2*j+1], pf[k16], vh[2], vh[3]);
                }
            }
        }

        // ---- softmax(kt+1) -> pf (for next iteration's PV) ----
        if (doS) softmax_tile(kt + 1, s);

        if (has_next) {
            CP_WAIT(0);        // kt+2 landed (if issued)
            __syncthreads();   // all warps done reading buf(kt) -> reusable
        }
    }

    // ---- epilogue: quad-reduce row sums, normalize, store ----
    rs0 += __shfl_xor_sync(0xFFFFFFFFu, rs0, 1);
    rs0 += __shfl_xor_sync(0xFFFFFFFFu, rs0, 2);
    rs1 += __shfl_xor_sync(0xFFFFFFFFu, rs1, 1);
    rs1 += __shfl_xor_sync(0xFFFFFFFFu, rs1, 2);
    const float inv0 = 1.f / rs0;
    const float inv1 = 1.f / rs1;

    float* O0 = Out + ((size_t)(b * S_LEN + grow0)) * DH + tg * 2;
    float* O1 = Out + ((size_t)(b * S_LEN + grow1)) * DH + tg * 2;
    #pragma unroll
    for (int n = 0; n < 8; ++n) {
        *reinterpret_cast<float2*>(O0 + n * 8) = make_float2(o[n][0] * inv0, o[n][1] * inv0);
        *reinterpret_cast<float2*>(O1 + n * 8) = make_float2(o[n][2] * inv1, o[n][3] * inv1);
    }
}

extern "C" void kernel_launch(void* const* d_in, const int* in_sizes, int n_in,
                              void* d_out, int out_size)
{
    const float* Q  = (const float*)d_in[0];
    const float* K  = (const float*)d_in[1];
    const float* V  = (const float*)d_in[2];
    const float* Rw = (const float*)d_in[3];
    const float* Rb = (const float*)d_in[4];
    float* Out      = (float*)d_out;

    (void)in_sizes; (void)n_in; (void)out_size;

    prepass_cvt<<<1024, 256>>>(K, V);

    cudaFuncSetAttribute(attn_main,
                         cudaFuncAttributeMaxDynamicSharedMemorySize, SMEM_BYTES);
    attn_main<<<256, NT, SMEM_BYTES>>>(Q, Rw, Rb, Out);
}

// round 17
// speedup vs baseline: 1.1730x; 1.1730x over previous
#include <cuda_runtime.h>
#include <cuda_fp16.h>
#include <cstdint>

// Q/K/V: [16, 2048, 64] f32, R_w: [3,64], R_b: [3]; out: [16,2048,64] f32
#define S_LEN 2048
#define DH    64
#define NHEAD 16
#define BQ    128
#define BC    64
#define NT    256
#define PSTB  144           // padded f16 row stride in bytes (72 elems)
// C2 = (1/sqrt(512)) * log2(e)
#define C2 (0.04419417382415922f * 1.4426950408889634f)

// smem: two K/V buffers. Per buffer: KH at 0 (9216B), VH at 9216 (9216B).
#define BUFB   18432
#define OFF_VH 9216
#define SMEM_BYTES (2 * BUFB)

// ---- global scratch: f16 copies of K/V ----
__device__ __align__(16) __half g_Kh[NHEAD * S_LEN * DH];
__device__ __align__(16) __half g_Vh[NHEAD * S_LEN * DH];

// ---------------- helpers ----------------
static __device__ __forceinline__ uint32_t smem_u32(const void* p) {
    uint32_t a;
    asm("{ .reg .u64 t; cvta.to.shared.u64 t, %1; cvt.u32.u64 %0, t; }" : "=r"(a) : "l"(p));
    return a;
}
static __device__ __forceinline__ void ldm_x4(uint32_t* r, uint32_t addr) {
    asm volatile("ldmatrix.sync.aligned.m8n8.x4.shared.b16 {%0,%1,%2,%3}, [%4];"
        : "=r"(r[0]), "=r"(r[1]), "=r"(r[2]), "=r"(r[3]) : "r"(addr));
}
static __device__ __forceinline__ void ldm_x4_t(uint32_t* r, uint32_t addr) {
    asm volatile("ldmatrix.sync.aligned.m8n8.x4.trans.shared.b16 {%0,%1,%2,%3}, [%4];"
        : "=r"(r[0]), "=r"(r[1]), "=r"(r[2]), "=r"(r[3]) : "r"(addr));
}
static __device__ __forceinline__ void mma16816(float* d, const uint32_t* a, uint32_t b0, uint32_t b1) {
    asm volatile("mma.sync.aligned.m16n8k16.row.col.f32.f16.f16.f32 "
        "{%0,%1,%2,%3}, {%4,%5,%6,%7}, {%8,%9}, {%0,%1,%2,%3};"
        : "+f"(d[0]), "+f"(d[1]), "+f"(d[2]), "+f"(d[3])
        : "r"(a[0]), "r"(a[1]), "r"(a[2]), "r"(a[3]), "r"(b0), "r"(b1));
}
static __device__ __forceinline__ uint32_t pkh(float a, float b) {
    __half2 t = __floats2half2_rn(a, b);     // a -> low half
    return *reinterpret_cast<uint32_t*>(&t);
}
static __device__ __forceinline__ float ex2f(float x) {
    float r; asm("ex2.approx.f32 %0, %1;" : "=f"(r) : "f"(x)); return r;
}
#define CP16(dst, src) \
    asm volatile("cp.async.cg.shared.global [%0], [%1], 16;" :: "r"(dst), "l"(src))
#define CP_COMMIT() asm volatile("cp.async.commit_group;" ::: "memory")
#define CP_WAIT(n)  asm volatile("cp.async.wait_group %0;" :: "n"(n) : "memory")

// ---------------- pre-pass: K/V f32 -> f16, MLP=4 ----------------
__global__ void prepass_cvt(const float* __restrict__ K, const float* __restrict__ V)
{
    const int N4 = NHEAD * S_LEN * DH / 4;   // 524288
    const int HALF = N4 / 2;                 // 262144
    const int j = blockIdx.x * blockDim.x + threadIdx.x;   // 0..262143
    const float4* K4 = (const float4*)K;
    const float4* V4 = (const float4*)V;
    float4 k0 = K4[j], k1 = K4[j + HALF];
    float4 v0 = V4[j], v1 = V4[j + HALF];
    uint2* Kd = (uint2*)g_Kh;
    uint2* Vd = (uint2*)g_Vh;
    Kd[j]        = make_uint2(pkh(k0.x, k0.y), pkh(k0.z, k0.w));
    Kd[j + HALF] = make_uint2(pkh(k1.x, k1.y), pkh(k1.z, k1.w));
    Vd[j]        = make_uint2(pkh(v0.x, v0.y), pkh(v0.z, v0.w));
    Vd[j + HALF] = make_uint2(pkh(v1.x, v1.y), pkh(v1.z, v1.w));
}

// issue K+V tile kt into buffer (NT=256: 2+2 CP16 per thread)
static __device__ __forceinline__ void issue_kv(uint32_t sbuf, int b, int kt, int tid) {
    const int row = tid >> 2, h = (tid & 3) * 32;          // 32B quarter-row
    const size_t boff = ((size_t)(b * S_LEN + kt * BC + row)) * (DH * 2) + h;
    const uint32_t d = sbuf + row * PSTB + h;
    CP16(d,               (const char*)g_Kh + boff);
    CP16(d + 16,          (const char*)g_Kh + boff + 16);
    CP16(d + OFF_VH,      (const char*)g_Vh + boff);
    CP16(d + OFF_VH + 16, (const char*)g_Vh + boff + 16);
}

extern __shared__ char smdyn[];

__global__ __launch_bounds__(NT, 2)
void attn_main(const float* __restrict__ Q, const float* __restrict__ Rw,
               const float* __restrict__ Rb, float* __restrict__ Out)
{
    const int tid  = threadIdx.x;
    const int lane = tid & 31;
    const int w    = tid >> 5;       // 8 warps, warp w owns rows w*16..w*16+15

    // ---- efficiency-balanced schedule ----
    // Solo SMs (classes 108..147, ONE resident CTA = 8 warps, ~0.7x issue rate)
    // get medium jobs (~22 units). Paired SMs (2 CTAs = 16 warps) absorb the
    // extremes, pair sums <= 34 units. Every (qt,b) in [0,16)x[0,16) exactly once.
    int qt, b;
    {
        const int bid = (int)blockIdx.x;
        const int cls = bid % 148, inst = bid / 148;
        if (cls >= 108) {                    // solo: 40 medium jobs
            const int i = cls - 108;
            if (i < 16)      { qt = 11; b = i; }
            else if (i < 32) { qt = 10; b = i - 16; }
            else             { qt = 9;  b = i - 32; }          // b 0..7
        } else {
            const int p = cls;
            if (p < 64) {                    // qt{15,14,13,12} + qt{0,1,2,3}
                const int s = p >> 4;        // 0..3
                b = p & 15;
                qt = inst ? s : (15 - s);
            } else if (p < 72) {             // qt9(b8..15) + qt4(b0..7)
                const int i = p - 64;
                if (inst) { qt = 4; b = i; } else { qt = 9; b = 8 + i; }
            } else if (p < 80) {             // qt8(b0..7) + qt4(b8..15)
                const int i = p - 72;
                if (inst) { qt = 4; b = 8 + i; } else { qt = 8; b = i; }
            } else if (p < 88) {             // qt8(b8..15) + qt5(b0..7)
                const int i = p - 80;
                if (inst) { qt = 5; b = i; } else { qt = 8; b = 8 + i; }
            } else if (p < 96) {             // qt7(b0..7) + qt5(b8..15)
                const int i = p - 88;
                if (inst) { qt = 5; b = 8 + i; } else { qt = 7; b = i; }
            } else if (p < 104) {            // qt7(b8..15) + qt6(b0..7)
                const int i = p - 96;
                if (inst) { qt = 6; b = i; } else { qt = 7; b = 8 + i; }
            } else {                         // qt6(b8..11) + qt6(b12..15)
                const int i = p - 104;
                qt = 6; b = inst ? (12 + i) : (8 + i);
            }
        }
    }
    const int ntiles = 2 * qt + 2;
    const uint32_t sb = smem_u32(smdyn);

    // ---- prologue: prefetch K/V tile 0 ----
    issue_kv(sb, b, 0, tid);
    CP_COMMIT();

    // ---- biases from f32 Q, in-warp (lane pair 2r,2r+1 -> row w*16+r) ----
    const int g = lane >> 2, tg = lane & 3;
    const int grow0 = qt * BQ + w * 16 + g;
    const int grow1 = grow0 + 8;
    const int wmax  = qt * BQ + w * 16 + 15;   // warp's max query row
    float bb0_0, bb1_0, bb0_1, bb1_1;
    {
        const int r = lane >> 1, h = (lane & 1) * 32;
        const float* q = Q + ((size_t)(b * S_LEN + qt * BQ + w * 16 + r)) * DH + h;
        float s0 = 0.f, s1 = 0.f;
        #pragma unroll
        for (int i = 0; i < 8; ++i) {
            float4 v = reinterpret_cast<const float4*>(q)[i];
            const int cc = h + 4 * i;
            s0 = fmaf(v.x, __ldg(Rw + cc+0), s0); s0 = fmaf(v.y, __ldg(Rw + cc+1), s0);
            s0 = fmaf(v.z, __ldg(Rw + cc+2), s0); s0 = fmaf(v.w, __ldg(Rw + cc+3), s0);
            s1 = fmaf(v.x, __ldg(Rw + 64+cc+0), s1); s1 = fmaf(v.y, __ldg(Rw + 64+cc+1), s1);
            s1 = fmaf(v.z, __ldg(Rw + 64+cc+2), s1); s1 = fmaf(v.w, __ldg(Rw + 64+cc+3), s1);
        }
        s0 += __shfl_xor_sync(0xFFFFFFFFu, s0, 1);
        s1 += __shfl_xor_sync(0xFFFFFFFFu, s1, 1);
        s0 = (s0 + __ldg(Rb + 0)) * C2;
        s1 = (s1 + __ldg(Rb + 1)) * C2;
        bb0_0 = __shfl_sync(0xFFFFFFFFu, s0, 2 * g);
        bb1_0 = __shfl_sync(0xFFFFFFFFu, s1, 2 * g);
        bb0_1 = __shfl_sync(0xFFFFFFFFu, s0, 2 * g + 16);
        bb1_1 = __shfl_sync(0xFFFFFFFFu, s1, 2 * g + 16);
    }

    // ---- Q fragments straight from f32 global ----
    uint32_t qf[4][4];
    {
        const float* Qlo = Q + ((size_t)(b * S_LEN + grow0)) * DH;
        const float* Qhi = Q + ((size_t)(b * S_LEN + grow1)) * DH;
        #pragma unroll
        for (int k16 = 0; k16 < 4; ++k16) {
            const int cc = k16 * 16 + tg * 2;
            float2 vlo0 = *reinterpret_cast<const float2*>(Qlo + cc);
            float2 vhi0 = *reinterpret_cast<const float2*>(Qhi + cc);
            float2 vlo1 = *reinterpret_cast<const float2*>(Qlo + cc + 8);
            float2 vhi1 = *reinterpret_cast<const float2*>(Qhi + cc + 8);
            qf[k16][0] = pkh(vlo0.x, vlo0.y);
            qf[k16][1] = pkh(vhi0.x, vhi0.y);
            qf[k16][2] = pkh(vlo1.x, vlo1.y);
            qf[k16][3] = pkh(vhi1.x, vhi1.y);
        }
    }

    float o[8][4];
    #pragma unroll
    for (int n = 0; n < 8; ++n)
        #pragma unroll
        for (int e = 0; e < 4; ++e) o[n][e] = 0.f;
    float rs0 = 0.f, rs1 = 0.f;

    const int rowK  = ((lane & 16) ? 8 : 0) + (lane & 7);
    const int colK8 = (lane & 8) ? 8 : 0;
    const int rowV  = lane & 15;
    const int colV8 = (lane & 16) ? 8 : 0;

    CP_WAIT(0);
    __syncthreads();           // K/V tile 0 visible

    for (int kt = 0; kt < ntiles; ++kt) {
        const uint32_t bcur = sb + (uint32_t)((kt & 1) * BUFB);
        const int has_next = (kt + 1 < ntiles);

        if (has_next) { issue_kv(sb + (uint32_t)(((kt + 1) & 1) * BUFB), b, kt + 1, tid); CP_COMMIT(); }

        // Skip fully-masked warp-tiles (diagonal tile 2qt+1 for warps 0-3)
        if (kt * BC <= wmax) {
            // ---- S = Q K^T (single-pass f16, f32 accumulate) ----
            float s[8][4];
            #pragma unroll
            for (int n = 0; n < 8; ++n)
                #pragma unroll
                for (int e = 0; e < 4; ++e) s[n][e] = 0.f;

            #pragma unroll
            for (int k16 = 0; k16 < 4; ++k16) {
                #pragma unroll
                for (int j = 0; j < 4; ++j) {
                    const uint32_t ak = bcur + (uint32_t)((16 * j + rowK) * PSTB)
                                      + (uint32_t)((k16 * 16 + colK8) * 2);
                    uint32_t kh[4];
                    ldm_x4(kh, ak);
                    mma16816(s[2*j],   qf[k16], kh[0], kh[1]);
                    mma16816(s[2*j+1], qf[k16], kh[2], kh[3]);
                }
            }

            // ---- softmax (fixed max 0, log2 domain) ----
            if (kt < 2 * qt) {     // every key strictly below all rows of this tile
                #pragma unroll
                for (int n = 0; n < 8; ++n) {
                    float p0 = ex2f(fmaf(s[n][0], C2, bb0_0));
                    float p1 = ex2f(fmaf(s[n][1], C2, bb0_0));
                    float p2 = ex2f(fmaf(s[n][2], C2, bb0_1));
                    float p3 = ex2f(fmaf(s[n][3], C2, bb0_1));
                    s[n][0] = p0; s[n][1] = p1; s[n][2] = p2; s[n][3] = p3;
                    rs0 += p0 + p1;
                    rs1 += p2 + p3;
                }
            } else {
                #pragma unroll
                for (int n = 0; n < 8; ++n) {
                    const int c0 = kt * BC + n * 8 + tg * 2;
                    const int c1 = c0 + 1;
                    float p;
                    p = (c0 > grow0) ? 0.f : ex2f(fmaf(s[n][0], C2, (c0 == grow0) ? bb1_0 : bb0_0));
                    s[n][0] = p; rs0 += p;
                    p = (c1 > grow0) ? 0.f : ex2f(fmaf(s[n][1], C2, (c1 == grow0) ? bb1_0 : bb0_0));
                    s[n][1] = p; rs0 += p;
                    p = (c0 > grow1) ? 0.f : ex2f(fmaf(s[n][2], C2, (c0 == grow1) ? bb1_1 : bb0_1));
                    s[n][2] = p; rs1 += p;
                    p = (c1 > grow1) ? 0.f : ex2f(fmaf(s[n][3], C2, (c1 == grow1) ? bb1_1 : bb0_1));
                    s[n][3] = p; rs1 += p;
                }
            }

            // ---- O += P V (P packed per-k16) ----
            #pragma unroll
            for (int k16 = 0; k16 < 4; ++k16) {
                uint32_t pf[4];
                #pragma unroll
                for (int e = 0; e < 2; ++e) {
                    float* sv = s[2*k16 + e];
                    pf[2*e]     = pkh(sv[0], sv[1]);
                    pf[2*e + 1] = pkh(sv[2], sv[3]);
                }
                #pragma unroll
                for (int j = 0; j < 4; ++j) {
                    const uint32_t av = bcur + OFF_VH + (uint32_t)((16 * k16 + rowV) * PSTB)
                                      + (uint32_t)((16 * j + colV8) * 2);
                    uint32_t vh[4];
                    ldm_x4_t(vh, av);
                    mma16816(o[2*j],   pf, vh[0], vh[1]);
                    mma16816(o[2*j+1], pf, vh[2], vh[3]);
                }
            }
        }

        if (has_next) {
            CP_WAIT(0);        // next tile landed
            __syncthreads();   // all warps done with current buffer
        }
    }

    // ---- epilogue: quad-reduce row sums, normalize, store ----
    rs0 += __shfl_xor_sync(0xFFFFFFFFu, rs0, 1);
    rs0 += __shfl_xor_sync(0xFFFFFFFFu, rs0, 2);
    rs1 += __shfl_xor_sync(0xFFFFFFFFu, rs1, 1);
    rs1 += __shfl_xor_sync(0xFFFFFFFFu, rs1, 2);
    const float inv0 = 1.f / rs0;
    const float inv1 = 1.f / rs1;

    float* O0 = Out + ((size_t)(b * S_LEN + grow0)) * DH + tg * 2;
    float* O1 = Out + ((size_t)(b * S_LEN + grow1)) * DH + tg * 2;
    #pragma unroll
    for (int n = 0; n < 8; ++n) {
        *reinterpret_cast<float2*>(O0 + n * 8) = make_float2(o[n][0] * inv0, o[n][1] * inv0);
        *reinterpret_cast<float2*>(O1 + n * 8) = make_float2(o[n][2] * inv1, o[n][3] * inv1);
    }
}

extern "C" void kernel_launch(void* const* d_in, const int* in_sizes, int n_in,
                              void* d_out, int out_size)
{
    const float* Q  = (const float*)d_in[0];
    const float* K  = (const float*)d_in[1];
    const float* V  = (const float*)d_in[2];
    const float* Rw = (const float*)d_in[3];
    const float* Rb = (const float*)d_in[4];
    float* Out      = (float*)d_out;

    (void)in_sizes; (void)n_in; (void)out_size;

    prepass_cvt<<<1024, 256>>>(K, V);

    attn_main<<<256, NT, SMEM_BYTES>>>(Q, Rw, Rb, Out);
}